// round 15
// baseline (speedup 1.0000x reference)
#include <cuda_runtime.h>

// ---------------------------------------------------------------------------
// OpticalFlowLoss: smem-free shuffle-stencil kernel (sm_103a)
// pred, gt: [B=8, T=8, C=3, H=256, W=256] fp32 -> scalar fp32 loss
// Warp = 128 contiguous pixels of one row (4/lane). Sobel horizontal
// neighbors via warp shuffle; vertical via direct row loads (L1-cached).
// No shared memory, no __syncthreads in the hot path.
// ---------------------------------------------------------------------------

#define B_    8
#define T_    8
#define H_    256
#define W_    256
#define HW_   (H_ * W_)          // 65536
#define FRAME_STRIDE (3 * HW_)
#define NPAIRS (B_ * (T_ - 1))   // 56

#define ROWS_PER_CTA 4
#define NBLOCKS ((H_ / ROWS_PER_CTA) * NPAIRS)   // 64*56 = 3584

#define EPSF 1e-3f
#define MEAN_COUNT 7340032.0     // 8*7*2*256*256

__device__ double g_accum;       // zero-init; self-resetting
__device__ unsigned int g_done;  // zero-init; self-resetting

__device__ __forceinline__ float gray3(float r, float g, float b) {
    return 0.2989f * r + 0.587f * g + 0.114f * b;
}

// Load one gray row segment with halo: lane covers cols c0..c0+3; v[0..5] =
// gray at cols c0-1 .. c0+4 (zero outside image). Also returns the RGB float4s.
__device__ __forceinline__ void grayRow(const float* __restrict__ img, int base,
                                        int hh, int c0, int lane,
                                        float4& r, float4& g, float4& b,
                                        float* v)
{
    bool in = ((unsigned)hh < H_);
    r = make_float4(0.f, 0.f, 0.f, 0.f);
    g = r; b = r;
    int off = base + hh * W_ + c0;
    if (in) {
        r = __ldg((const float4*)(img + off));
        g = __ldg((const float4*)(img + off + HW_));
        b = __ldg((const float4*)(img + off + 2 * HW_));
    }
    v[1] = gray3(r.x, g.x, b.x);
    v[2] = gray3(r.y, g.y, b.y);
    v[3] = gray3(r.z, g.z, b.z);
    v[4] = gray3(r.w, g.w, b.w);

    float left  = __shfl_up_sync(0xFFFFFFFFu, v[4], 1);
    float right = __shfl_down_sync(0xFFFFFFFFu, v[1], 1);
    if (lane == 0) {
        left = 0.f;
        if (in && c0 > 0) {
            int o = off - 1;
            left = gray3(__ldg(img + o), __ldg(img + o + HW_), __ldg(img + o + 2 * HW_));
        }
    }
    if (lane == 31) {
        right = 0.f;
        if (in && c0 + 4 < W_) {
            int o = off + 4;
            right = gray3(__ldg(img + o), __ldg(img + o + HW_), __ldg(img + o + 2 * HW_));
        }
    }
    v[0] = left;
    v[5] = right;
}

__global__ __launch_bounds__(256)
void flow_loss_kernel(const float* __restrict__ pred,
                      const float* __restrict__ gt,
                      float* __restrict__ out) {
    const int pair = blockIdx.z;          // 0..55
    const int b = pair / (T_ - 1);
    const int t = pair % (T_ - 1);

    const int base1 = (b * T_ + t) * FRAME_STRIDE;  // frame t
    const int base2 = base1 + FRAME_STRIDE;         // frame t+1

    const int tid  = threadIdx.x;
    const int wid  = tid >> 5;
    const int lane = tid & 31;
    const int h    = blockIdx.y * ROWS_PER_CTA + (wid >> 1);  // image row
    const int c0   = (wid & 1) * 128 + lane * 4;              // first col

    float4 d0, d1, d2;  // scratch rgb

    // ---- pred: 3 gray rows (t) + center gray (t+1) ----
    float p0[6], p1[6], p2[6];
    grayRow(pred, base1, h - 1, c0, lane, d0, d1, d2, p0);
    grayRow(pred, base1, h,     c0, lane, d0, d1, d2, p1);
    grayRow(pred, base1, h + 1, c0, lane, d0, d1, d2, p2);

    int off2 = base2 + h * W_ + c0;
    float4 pr2 = __ldg((const float4*)(pred + off2));
    float4 pg2 = __ldg((const float4*)(pred + off2 + HW_));
    float4 pb2 = __ldg((const float4*)(pred + off2 + 2 * HW_));
    float gyP2[4] = {gray3(pr2.x, pg2.x, pb2.x), gray3(pr2.y, pg2.y, pb2.y),
                     gray3(pr2.z, pg2.z, pb2.z), gray3(pr2.w, pg2.w, pb2.w)};

    // ---- gt: 3 gray rows (t) keeping middle RGB, + RGB (t+1) ----
    float q0[6], q1[6], q2[6];
    float4 gr1, gg1, gb1;
    grayRow(gt, base1, h - 1, c0, lane, d0, d1, d2, q0);
    grayRow(gt, base1, h,     c0, lane, gr1, gg1, gb1, q1);
    grayRow(gt, base1, h + 1, c0, lane, d0, d1, d2, q2);

    float4 gr2 = __ldg((const float4*)(gt + off2));
    float4 gg2 = __ldg((const float4*)(gt + off2 + HW_));
    float4 gb2 = __ldg((const float4*)(gt + off2 + 2 * HW_));
    float gyG2[4] = {gray3(gr2.x, gg2.x, gb2.x), gray3(gr2.y, gg2.y, gb2.y),
                     gray3(gr2.z, gg2.z, gb2.z), gray3(gr2.w, gg2.w, gb2.w)};

    float mr1[4] = {gr1.x, gr1.y, gr1.z, gr1.w};
    float mg1[4] = {gg1.x, gg1.y, gg1.z, gg1.w};
    float mb1[4] = {gb1.x, gb1.y, gb1.z, gb1.w};
    float mr2[4] = {gr2.x, gr2.y, gr2.z, gr2.w};
    float mg2[4] = {gg2.x, gg2.y, gg2.z, gg2.w};
    float mb2[4] = {gb2.x, gb2.y, gb2.z, gb2.w};

    float acc = 0.0f;

    #pragma unroll
    for (int p = 0; p < 4; ++p) {
        float IxP = (p0[p] - p0[p + 2]) + 2.0f * (p1[p] - p1[p + 2])
                  + (p2[p] - p2[p + 2]);
        float IyP = (p0[p] + 2.0f * p0[p + 1] + p0[p + 2])
                  - (p2[p] + 2.0f * p2[p + 1] + p2[p + 2]);
        float ItP = gyP2[p] - p1[p + 1];
        float invP = __fdividef(1.0f, IxP * IxP + IyP * IyP + EPSF);
        float uP = -IxP * ItP * invP;
        float vP = -IyP * ItP * invP;

        float IxG = (q0[p] - q0[p + 2]) + 2.0f * (q1[p] - q1[p + 2])
                  + (q2[p] - q2[p + 2]);
        float IyG = (q0[p] + 2.0f * q0[p + 1] + q0[p + 2])
                  - (q2[p] + 2.0f * q2[p + 1] + q2[p + 2]);
        float ItG = gyG2[p] - q1[p + 1];
        float invG = __fdividef(1.0f, IxG * IxG + IyG * IyG + EPSF);
        float uG = -IxG * ItG * invG;
        float vG = -IyG * ItG * invG;

        float mm = (fabsf(mr2[p] - mr1[p]) + fabsf(mg2[p] - mg1[p])
                  + fabsf(mb2[p] - mb1[p])) * (1.0f / 3.0f);

        acc += (fabsf(uP - uG) + fabsf(vP - vG)) * mm;
    }

    // --- block reduction ---
    #pragma unroll
    for (int s = 16; s > 0; s >>= 1)
        acc += __shfl_xor_sync(0xFFFFFFFFu, acc, s);

    __shared__ float warpSum[8];
    if (lane == 0) warpSum[wid] = acc;
    __syncthreads();

    if (tid == 0) {
        float v = 0.0f;
        #pragma unroll
        for (int j = 0; j < 8; ++j) v += warpSum[j];
        atomicAdd(&g_accum, (double)v);
        __threadfence();
        unsigned ticket = atomicAdd(&g_done, 1u);
        if (ticket == NBLOCKS - 1) {
            out[0] = (float)(g_accum / MEAN_COUNT);
            g_accum = 0.0;
            __threadfence();
            g_done = 0u;
        }
    }
}

extern "C" void kernel_launch(void* const* d_in, const int* in_sizes, int n_in,
                              void* d_out, int out_size) {
    const float* pred = (const float*)d_in[0];
    const float* gt   = (const float*)d_in[1];
    float* out = (float*)d_out;

    dim3 grid(1, H_ / ROWS_PER_CTA, NPAIRS);  // (1, 64, 56) = 3584 CTAs
    flow_loss_kernel<<<grid, 256>>>(pred, gt, out);
}

// round 16
// speedup vs baseline: 1.3845x; 1.3845x over previous
#include <cuda_runtime.h>

// ---------------------------------------------------------------------------
// OpticalFlowLoss fused single-kernel, 4x vectorized (sm_103a)
// R6 skeleton + vertically-paired chunks (rows ly, ly+1) for smem-LDS CSE
// + tightened live ranges on the point loads (register diet, natural regs).
// pred, gt: [B=8, T=8, C=3, H=256, W=256] fp32 -> scalar fp32 loss
// ---------------------------------------------------------------------------

#define B_    8
#define T_    8
#define H_    256
#define W_    256
#define HW_   (H_ * W_)          // 65536
#define FRAME_STRIDE (3 * HW_)
#define NPAIRS (B_ * (T_ - 1))   // 56

#define TILE_W 64
#define TILE_H 32
#define HALO_H (TILE_H + 2)      // 34
#define SCOLS  72                // covers global cols tileX-4 .. tileX+67
#define SLOTS  (SCOLS / 4)       // 18 float4 slots per halo row

#define NBLOCKS ((W_ / TILE_W) * (H_ / TILE_H) * NPAIRS)  // 4*8*56 = 1792

#define EPSF 1e-3f
#define MEAN_COUNT 7340032.0     // 8*7*2*256*256

__device__ double g_accum;       // zero-init; self-resetting
__device__ unsigned int g_done;  // zero-init; self-resetting

__device__ __forceinline__ float gray3(float r, float g, float b) {
    return 0.2989f * r + 0.587f * g + 0.114f * b;
}

__device__ __forceinline__ float gray3v(const float4& r, const float4& g,
                                        const float4& b, int p) {
    const float* rr = (const float*)&r;
    const float* gg = (const float*)&g;
    const float* bb = (const float*)&b;
    return gray3(rr[p], gg[p], bb[p]);
}

__global__ __launch_bounds__(256)
void flow_loss_kernel(const float* __restrict__ pred,
                      const float* __restrict__ gt,
                      float* __restrict__ out) {
    const int pair = blockIdx.z;          // 0..55
    const int b = pair / (T_ - 1);
    const int t = pair % (T_ - 1);

    const int tileX = blockIdx.x * TILE_W;
    const int tileY = blockIdx.y * TILE_H;

    const int base1 = (b * T_ + t) * FRAME_STRIDE;  // frame t
    const int base2 = base1 + FRAME_STRIDE;         // frame t+1

    __shared__ float sP[HALO_H][SCOLS];
    __shared__ float sG[HALO_H][SCOLS];

    // --- vectorized halo fill: gray of frame t for pred and gt ---
    for (int i = threadIdx.x; i < HALO_H * SLOTS; i += 256) {
        int hy = i / SLOTS;
        int sl = i - hy * SLOTS;
        int gh = tileY + hy - 1;
        int gc = tileX - 4 + sl * 4;
        float4 vp = make_float4(0.f, 0.f, 0.f, 0.f);
        float4 vg = vp;
        if ((unsigned)gh < H_ && (unsigned)gc < W_) {
            int off = base1 + gh * W_ + gc;
            float4 r = __ldg((const float4*)(pred + off));
            float4 g = __ldg((const float4*)(pred + off + HW_));
            float4 bb = __ldg((const float4*)(pred + off + 2 * HW_));
            vp = make_float4(gray3(r.x, g.x, bb.x), gray3(r.y, g.y, bb.y),
                             gray3(r.z, g.z, bb.z), gray3(r.w, g.w, bb.w));
            r  = __ldg((const float4*)(gt + off));
            g  = __ldg((const float4*)(gt + off + HW_));
            bb = __ldg((const float4*)(gt + off + 2 * HW_));
            vg = make_float4(gray3(r.x, g.x, bb.x), gray3(r.y, g.y, bb.y),
                             gray3(r.z, g.z, bb.z), gray3(r.w, g.w, bb.w));
        }
        *(float4*)&sP[hy][sl * 4] = vp;
        *(float4*)&sG[hy][sl * 4] = vg;
    }
    __syncthreads();

    // Two vertically adjacent chunks: rows ly0 and ly0+1, cols sx..sx+3.
    const int ly0 = (threadIdx.x >> 4) * 2;   // 0,2,..,30
    const int sx  = (threadIdx.x & 15) * 4;   // 0..60

    float acc = 0.0f;

    #pragma unroll
    for (int k = 0; k < 2; ++k) {
        const int ly = ly0 + k;
        const int off = (tileY + ly) * W_ + tileX + sx;
        const int off2 = base2 + off;
        const int off1 = base1 + off;

        // ---- point loads, folded immediately into scalars ----
        float gyP2[4], gyG2[4], mm[4];
        {
            float4 pr2 = __ldg((const float4*)(pred + off2));
            float4 pg2 = __ldg((const float4*)(pred + off2 + HW_));
            float4 pb2 = __ldg((const float4*)(pred + off2 + 2 * HW_));
            float4 gr2 = __ldg((const float4*)(gt + off2));
            float4 gg2 = __ldg((const float4*)(gt + off2 + HW_));
            float4 gb2 = __ldg((const float4*)(gt + off2 + 2 * HW_));
            float4 gr1 = __ldg((const float4*)(gt + off1));
            float4 gg1 = __ldg((const float4*)(gt + off1 + HW_));
            float4 gb1 = __ldg((const float4*)(gt + off1 + 2 * HW_));

            #pragma unroll
            for (int p = 0; p < 4; ++p) {
                gyP2[p] = gray3v(pr2, pg2, pb2, p);
                gyG2[p] = gray3v(gr2, gg2, gb2, p);
                const float* a;
                a = (const float*)&gr2; float dr = a[p];
                a = (const float*)&gr1; dr -= a[p];
                a = (const float*)&gg2; float dg = a[p];
                a = (const float*)&gg1; dg -= a[p];
                a = (const float*)&gb2; float db = a[p];
                a = (const float*)&gb1; db -= a[p];
                mm[p] = (fabsf(dr) + fabsf(dg) + fabsf(db)) * (1.0f / 3.0f);
            }
        }

        // ---- pred Sobel + flow ----
        float uP[4], vP[4];
        {
            float4 a0 = *(const float4*)&sP[ly    ][sx];
            float4 m0 = *(const float4*)&sP[ly    ][sx + 4];
            float  c0 = sP[ly    ][sx + 8];
            float4 a1 = *(const float4*)&sP[ly + 1][sx];
            float4 m1 = *(const float4*)&sP[ly + 1][sx + 4];
            float  c1 = sP[ly + 1][sx + 8];
            float4 a2 = *(const float4*)&sP[ly + 2][sx];
            float4 m2 = *(const float4*)&sP[ly + 2][sx + 4];
            float  c2 = sP[ly + 2][sx + 8];
            float t0[6] = {a0.w, m0.x, m0.y, m0.z, m0.w, c0};
            float t1[6] = {a1.w, m1.x, m1.y, m1.z, m1.w, c1};
            float t2[6] = {a2.w, m2.x, m2.y, m2.z, m2.w, c2};
            #pragma unroll
            for (int p = 0; p < 4; ++p) {
                float Ix = (t0[p] - t0[p + 2]) + 2.0f * (t1[p] - t1[p + 2])
                         + (t2[p] - t2[p + 2]);
                float Iy = (t0[p] + 2.0f * t0[p + 1] + t0[p + 2])
                         - (t2[p] + 2.0f * t2[p + 1] + t2[p + 2]);
                float It = gyP2[p] - t1[p + 1];
                float inv = __fdividef(1.0f, Ix * Ix + Iy * Iy + EPSF);
                uP[p] = -Ix * It * inv;
                vP[p] = -Iy * It * inv;
            }
        }

        // ---- gt Sobel + flow + accumulate ----
        {
            float4 a0 = *(const float4*)&sG[ly    ][sx];
            float4 m0 = *(const float4*)&sG[ly    ][sx + 4];
            float  c0 = sG[ly    ][sx + 8];
            float4 a1 = *(const float4*)&sG[ly + 1][sx];
            float4 m1 = *(const float4*)&sG[ly + 1][sx + 4];
            float  c1 = sG[ly + 1][sx + 8];
            float4 a2 = *(const float4*)&sG[ly + 2][sx];
            float4 m2 = *(const float4*)&sG[ly + 2][sx + 4];
            float  c2 = sG[ly + 2][sx + 8];
            float t0[6] = {a0.w, m0.x, m0.y, m0.z, m0.w, c0};
            float t1[6] = {a1.w, m1.x, m1.y, m1.z, m1.w, c1};
            float t2[6] = {a2.w, m2.x, m2.y, m2.z, m2.w, c2};
            #pragma unroll
            for (int p = 0; p < 4; ++p) {
                float Ix = (t0[p] - t0[p + 2]) + 2.0f * (t1[p] - t1[p + 2])
                         + (t2[p] - t2[p + 2]);
                float Iy = (t0[p] + 2.0f * t0[p + 1] + t0[p + 2])
                         - (t2[p] + 2.0f * t2[p + 1] + t2[p + 2]);
                float It = gyG2[p] - t1[p + 1];
                float inv = __fdividef(1.0f, Ix * Ix + Iy * Iy + EPSF);
                float uG = -Ix * It * inv;
                float vG = -Iy * It * inv;
                acc += (fabsf(uP[p] - uG) + fabsf(vP[p] - vG)) * mm[p];
            }
        }
    }

    // --- block reduction ---
    #pragma unroll
    for (int s = 16; s > 0; s >>= 1)
        acc += __shfl_xor_sync(0xFFFFFFFFu, acc, s);

    __shared__ float warpSum[8];
    int lane = threadIdx.x & 31;
    int wid  = threadIdx.x >> 5;
    if (lane == 0) warpSum[wid] = acc;
    __syncthreads();

    if (wid == 0 && lane == 0) {
        float v = 0.0f;
        #pragma unroll
        for (int j = 0; j < 8; ++j) v += warpSum[j];
        atomicAdd(&g_accum, (double)v);
        __threadfence();
        unsigned ticket = atomicAdd(&g_done, 1u);
        if (ticket == NBLOCKS - 1) {
            out[0] = (float)(g_accum / MEAN_COUNT);
            g_accum = 0.0;
            __threadfence();
            g_done = 0u;
        }
    }
}

extern "C" void kernel_launch(void* const* d_in, const int* in_sizes, int n_in,
                              void* d_out, int out_size) {
    const float* pred = (const float*)d_in[0];
    const float* gt   = (const float*)d_in[1];
    float* out = (float*)d_out;

    dim3 grid(W_ / TILE_W, H_ / TILE_H, NPAIRS);  // (4, 8, 56) = 1792 CTAs
    flow_loss_kernel<<<grid, 256>>>(pred, gt, out);
}